// round 2
// baseline (speedup 1.0000x reference)
#include <cuda_runtime.h>
#include <math.h>

#define N_STATE 131072
#define H 128

#define K1_COLS 256
#define K1_BLOCKS (N_STATE / K1_COLS)          // 512
#define K1_THREADS 256

#define K2_THREADS 512

#define K3_THREADS 128
#define K3_BLOCKS (N_STATE / 4 / K3_THREADS)   // 256

// Scratch (allocation-free: __device__ globals)
__device__ float g_part[K1_BLOCKS * H];        // per-block partial dot products
__device__ float g_u[H];                       // composed Jacobian row vector

// ---------------------------------------------------------------------------
// Kernel 1: partial matvec  g_part[b][i] = sum_{j in chunk b} W0[i,j] * xn[j]
// xn[j] = (2*state[j] - (xmax+xmin)) / (xmax - xmin), computed inline.
// Each block owns a 256-column chunk for all 128 rows. 8 warps x 16 rows.
// All 32 LDG.128 per warp are independent (reductions deferred) -> high MLP.
// ---------------------------------------------------------------------------
__global__ void __launch_bounds__(K1_THREADS) k1_matvec(
        const float* __restrict__ state,
        const float* __restrict__ xmax,
        const float* __restrict__ xmin,
        const float* __restrict__ W0) {
    __shared__ __align__(16) float xn_s[K1_COLS];
    const int c0 = blockIdx.x * K1_COLS;

    {
        int j = c0 + threadIdx.x;                 // K1_THREADS == K1_COLS
        float mx = xmax[j], mn = xmin[j];
        xn_s[threadIdx.x] = (2.0f * state[j] - (mx + mn)) / (mx - mn);
    }
    __syncthreads();

    const int lane = threadIdx.x & 31;
    const int warp = threadIdx.x >> 5;            // 0..7
    const float4* __restrict__ W4 = (const float4*)W0;
    const float4* __restrict__ x4 = (const float4*)xn_s;
    const int rs4 = N_STATE / 4;
    const int c04 = c0 / 4;

    float acc[16];
    #pragma unroll
    for (int rr = 0; rr < 16; rr++) acc[rr] = 0.f;

    #pragma unroll
    for (int rr = 0; rr < 16; rr++) {
        const int r = warp * 16 + rr;
        #pragma unroll
        for (int k = 0; k < K1_COLS / 128; k++) {   // 2 iters
            float4 w = W4[r * rs4 + c04 + k * 32 + lane];
            float4 x = x4[k * 32 + lane];
            acc[rr] += w.x * x.x + w.y * x.y + w.z * x.z + w.w * x.w;
        }
    }

    #pragma unroll
    for (int rr = 0; rr < 16; rr++) {
        float a = acc[rr];
        #pragma unroll
        for (int off = 16; off; off >>= 1)
            a += __shfl_down_sync(0xffffffffu, a, off);
        if (lane == 0) g_part[blockIdx.x * H + warp * 16 + rr] = a;
    }
}

// ---------------------------------------------------------------------------
// Kernel 2 (1 block, 512 threads): finish V0, run the small dense chain
// forward (collect tanh' diagonals d0,d1,d2 and scalar h), then compose
// u = D0 * W1^T * D1 * W2^T * D2 * W3^T * Wout^T (as row-vector products).
// ---------------------------------------------------------------------------
__device__ __forceinline__ void fwd_matvec(
        const float* __restrict__ W, const float* __restrict__ b,
        const float* __restrict__ v, float* __restrict__ nv,
        int warp, int lane) {
    // 16 warps, each handles 8 rows. Row r: lanes stride the 128 columns.
    float acc[8];
    #pragma unroll
    for (int rr = 0; rr < 8; rr++) acc[rr] = 0.f;
    #pragma unroll
    for (int rr = 0; rr < 8; rr++) {
        const int r = warp * 8 + rr;
        #pragma unroll
        for (int k = 0; k < 4; k++)
            acc[rr] += W[r * H + k * 32 + lane] * v[k * 32 + lane];
    }
    #pragma unroll
    for (int rr = 0; rr < 8; rr++) {
        float a = acc[rr];
        #pragma unroll
        for (int off = 16; off; off >>= 1)
            a += __shfl_down_sync(0xffffffffu, a, off);
        if (lane == 0) {
            const int r = warp * 8 + rr;
            nv[r] = a + b[r];
        }
    }
}

__global__ void __launch_bounds__(K2_THREADS) k2_chain(
        const float* __restrict__ b0v,
        const float* __restrict__ W1, const float* __restrict__ b1v,
        const float* __restrict__ W2, const float* __restrict__ b2v,
        const float* __restrict__ W3, const float* __restrict__ b3v,
        const float* __restrict__ Wout, const float* __restrict__ boutv,
        float* __restrict__ out) {
    __shared__ float v[H], nv[H], dd0[H], dd1[H], dd2[H], us[H], nus[H];
    __shared__ float psum[4 * H];
    __shared__ float red[4];

    const int tid = threadIdx.x;
    const int lane = tid & 31;
    const int warp = tid >> 5;                    // 0..15

    // Phase A: reduce K1_BLOCKS partials (coalesced, 4-way thread-group split)
    {
        const int i = tid & (H - 1);
        const int g = tid >> 7;                   // 0..3
        float s = 0.f;
        #pragma unroll 8
        for (int b = g; b < K1_BLOCKS; b += 4)
            s += g_part[b * H + i];
        psum[g * H + i] = s;
    }
    __syncthreads();
    if (tid < H) {
        float s = psum[tid] + psum[H + tid] + psum[2 * H + tid] + psum[3 * H + tid] + b0v[tid];
        float a = tanhf(s);
        v[tid] = a;
        dd0[tid] = 1.f - a * a;
    }
    __syncthreads();

    // Forward: layer 0 (W1) + tanh
    fwd_matvec(W1, b1v, v, nv, warp, lane);
    __syncthreads();
    if (tid < H) { float a = tanhf(nv[tid]); v[tid] = a; dd1[tid] = 1.f - a * a; }
    __syncthreads();

    // Forward: layer 1 (W2) + tanh
    fwd_matvec(W2, b2v, v, nv, warp, lane);
    __syncthreads();
    if (tid < H) { float a = tanhf(nv[tid]); v[tid] = a; dd2[tid] = 1.f - a * a; }
    __syncthreads();

    // Forward: layer 2 (W3), no activation
    fwd_matvec(W3, b3v, v, nv, warp, lane);
    __syncthreads();
    if (tid < H) v[tid] = nv[tid];
    __syncthreads();

    // h = Wout . v + bout ; seed u = Wout
    if (tid < H) {
        float p = Wout[tid] * v[tid];
        #pragma unroll
        for (int off = 16; off; off >>= 1)
            p += __shfl_down_sync(0xffffffffu, p, off);
        if (lane == 0) red[warp] = p;             // warps 0..3
        us[tid] = Wout[tid];
    }
    __syncthreads();
    if (tid == 0) out[0] = red[0] + red[1] + red[2] + red[3] + boutv[0];

    // Backward composition (thread-per-column, coalesced; W rows hot in L2)
    if (tid < H) {
        float a = 0.f;
        #pragma unroll 8
        for (int i = 0; i < H; i++) a += W3[i * H + tid] * us[i];
        nus[tid] = a * dd2[tid];
    }
    __syncthreads();
    if (tid < H) {
        float a = 0.f;
        #pragma unroll 8
        for (int i = 0; i < H; i++) a += W2[i * H + tid] * nus[i];
        us[tid] = a * dd1[tid];
    }
    __syncthreads();
    if (tid < H) {
        float a = 0.f;
        #pragma unroll 8
        for (int i = 0; i < H; i++) a += W1[i * H + tid] * us[i];
        g_u[tid] = a * dd0[tid];
    }
}

// ---------------------------------------------------------------------------
// Kernel 3: out[1+j] = (sum_i u[i] * W0[i,j]) * 2 / (xmax[j]-xmin[j])
// Thread-per-4-columns (float4); 128 independent LDG.128 per thread -> MLP max.
// W0 is hot in L2 from kernel 1 (64 MB fits the 126 MB L2).
// 256 blocks x 128 threads for full 148-SM coverage.
// ---------------------------------------------------------------------------
__global__ void __launch_bounds__(K3_THREADS) k3_out(
        const float* __restrict__ W0,
        const float* __restrict__ xmax,
        const float* __restrict__ xmin,
        float* __restrict__ out) {
    __shared__ float us[H];
    const int tid = threadIdx.x;
    if (tid < H) us[tid] = g_u[tid];
    __syncthreads();

    const int j4 = blockIdx.x * K3_THREADS + tid;      // float4 column index
    const float4* __restrict__ W4 = (const float4*)W0;
    const int rs4 = N_STATE / 4;

    float4 acc = make_float4(0.f, 0.f, 0.f, 0.f);
    #pragma unroll 8
    for (int i = 0; i < H; i++) {
        float4 w = W4[i * rs4 + j4];
        float ui = us[i];
        acc.x += ui * w.x;
        acc.y += ui * w.y;
        acc.z += ui * w.z;
        acc.w += ui * w.w;
    }

    float4 mx = ((const float4*)xmax)[j4];
    float4 mn = ((const float4*)xmin)[j4];
    const int j = j4 * 4;
    out[1 + j + 0] = acc.x * 2.f / (mx.x - mn.x);
    out[1 + j + 1] = acc.y * 2.f / (mx.y - mn.y);
    out[1 + j + 2] = acc.z * 2.f / (mx.z - mn.z);
    out[1 + j + 3] = acc.w * 2.f / (mx.w - mn.w);
}

// ---------------------------------------------------------------------------
extern "C" void kernel_launch(void* const* d_in, const int* in_sizes, int n_in,
                              void* d_out, int out_size) {
    const float* state = (const float*)d_in[0];
    const float* xmax  = (const float*)d_in[1];
    const float* xmin  = (const float*)d_in[2];
    const float* W0    = (const float*)d_in[3];
    const float* b0    = (const float*)d_in[4];
    const float* W1    = (const float*)d_in[5];
    const float* b1    = (const float*)d_in[6];
    const float* W2    = (const float*)d_in[7];
    const float* b2    = (const float*)d_in[8];
    const float* W3    = (const float*)d_in[9];
    const float* b3    = (const float*)d_in[10];
    const float* Wout  = (const float*)d_in[11];
    const float* bout  = (const float*)d_in[12];
    float* out = (float*)d_out;

    k1_matvec<<<K1_BLOCKS, K1_THREADS>>>(state, xmax, xmin, W0);
    k2_chain<<<1, K2_THREADS>>>(b0, W1, b1, W2, b2, W3, b3, Wout, bout, out);
    k3_out<<<K3_BLOCKS, K3_THREADS>>>(W0, xmax, xmin, out);
}

// round 4
// speedup vs baseline: 1.1209x; 1.1209x over previous
#include <cuda_runtime.h>
#include <math.h>

#define N_STATE 131072
#define H 128

#define K1_COLS 128
#define K1_BLOCKS (N_STATE / K1_COLS)          // 1024
#define K1_THREADS 256

#define K2_THREADS 1024

#define K3_THREADS 256
#define K3_C4_PER_BLOCK 32                     // float4 columns per block
#define K3_BLOCKS (N_STATE / 4 / K3_C4_PER_BLOCK)  // 1024

// Scratch (allocation-free: __device__ globals)
__device__ float g_part[K1_BLOCKS * H];        // per-block partial dot products
__device__ float g_u[H];                       // composed Jacobian row vector

// ---------------------------------------------------------------------------
// Kernel 1: partial matvec  g_part[b][i] = sum_{j in chunk b} W0[i,j] * xn[j]
// 1024 blocks x 128-col chunks -> 6.92 waves (98.9% balance).
// 8 warps x 16 rows; one float4 per lane per row -> 16 independent LDG.128
// per thread, reductions deferred to the end.
// ---------------------------------------------------------------------------
__global__ void __launch_bounds__(K1_THREADS, 4) k1_matvec(
        const float* __restrict__ state,
        const float* __restrict__ xmax,
        const float* __restrict__ xmin,
        const float* __restrict__ W0) {
    __shared__ __align__(16) float xn_s[K1_COLS];
    const int c0 = blockIdx.x * K1_COLS;
    const int tid = threadIdx.x;

    if (tid < K1_COLS) {
        int j = c0 + tid;
        float mx = xmax[j], mn = xmin[j];
        xn_s[tid] = (2.0f * state[j] - (mx + mn)) / (mx - mn);
    }
    __syncthreads();

    const int lane = tid & 31;
    const int warp = tid >> 5;                    // 0..7
    const float4* __restrict__ W4 = (const float4*)W0;
    const int rs4 = N_STATE / 4;
    const int c04 = c0 / 4;

    const float4 x = ((const float4*)xn_s)[lane];

    float acc[16];
    #pragma unroll
    for (int rr = 0; rr < 16; rr++) {
        const int r = warp * 16 + rr;
        float4 w = W4[r * rs4 + c04 + lane];
        acc[rr] = w.x * x.x + w.y * x.y + w.z * x.z + w.w * x.w;
    }

    #pragma unroll
    for (int rr = 0; rr < 16; rr++) {
        float a = acc[rr];
        #pragma unroll
        for (int off = 16; off; off >>= 1)
            a += __shfl_down_sync(0xffffffffu, a, off);
        if (lane == 0) g_part[blockIdx.x * H + warp * 16 + rr] = a;
    }
}

// ---------------------------------------------------------------------------
// Kernel 2 (1 block, 1024 threads): finish V0, forward chain (collect tanh'
// diagonals), backward composition  u = D0 W1^T D1 W2^T D2 W3^T Wout^T.
// ---------------------------------------------------------------------------
__device__ __forceinline__ void fwd_matvec(
        const float* __restrict__ W, const float* __restrict__ b,
        const float* __restrict__ v, float* __restrict__ nv,
        int warp, int lane) {
    // 32 warps x 4 rows; lanes stride 128 columns.
    float acc[4];
    #pragma unroll
    for (int rr = 0; rr < 4; rr++) {
        const int r = warp * 4 + rr;
        float a = 0.f;
        #pragma unroll
        for (int k = 0; k < 4; k++)
            a += W[r * H + k * 32 + lane] * v[k * 32 + lane];
        acc[rr] = a;
    }
    #pragma unroll
    for (int rr = 0; rr < 4; rr++) {
        float a = acc[rr];
        #pragma unroll
        for (int off = 16; off; off >>= 1)
            a += __shfl_down_sync(0xffffffffu, a, off);
        if (lane == 0) {
            const int r = warp * 4 + rr;
            nv[r] = a + b[r];
        }
    }
}

// Backward step: outv[c] = dd[c] * sum_i W[i*H + c] * usv[i]
// 256 threads participate: c4 = tid&31 (float4 column), ig = tid>>5 (8 row
// groups of 16). Coalesced float4 loads, 16 independent per thread.
__device__ __forceinline__ void bwd_matvec(
        const float* __restrict__ W,
        const float* __restrict__ usv,
        const float* __restrict__ dd,      // may be NULL (no scaling)
        float* __restrict__ outv,
        float4* __restrict__ part4,
        int tid) {
    if (tid < 256) {
        const int c4 = tid & 31;
        const int ig = tid >> 5;
        const float4* __restrict__ W4 = (const float4*)W;
        float4 a = make_float4(0.f, 0.f, 0.f, 0.f);
        #pragma unroll
        for (int k = 0; k < 16; k++) {
            const int i = ig * 16 + k;
            float4 w = W4[i * (H / 4) + c4];
            float ui = usv[i];
            a.x += ui * w.x; a.y += ui * w.y; a.z += ui * w.z; a.w += ui * w.w;
        }
        part4[tid] = a;
    }
    __syncthreads();
    if (tid < 32) {
        float4 s = make_float4(0.f, 0.f, 0.f, 0.f);
        #pragma unroll
        for (int g = 0; g < 8; g++) {
            float4 p = part4[g * 32 + tid];
            s.x += p.x; s.y += p.y; s.z += p.z; s.w += p.w;
        }
        const int c = tid * 4;
        if (dd) {
            outv[c + 0] = s.x * dd[c + 0];
            outv[c + 1] = s.y * dd[c + 1];
            outv[c + 2] = s.z * dd[c + 2];
            outv[c + 3] = s.w * dd[c + 3];
        } else {
            outv[c + 0] = s.x; outv[c + 1] = s.y;
            outv[c + 2] = s.z; outv[c + 3] = s.w;
        }
    }
    __syncthreads();
}

__global__ void __launch_bounds__(K2_THREADS) k2_chain(
        const float* __restrict__ b0v,
        const float* __restrict__ W1, const float* __restrict__ b1v,
        const float* __restrict__ W2, const float* __restrict__ b2v,
        const float* __restrict__ W3, const float* __restrict__ b3v,
        const float* __restrict__ Wout, const float* __restrict__ boutv,
        float* __restrict__ out) {
    __shared__ float v[H], nv[H], dd0[H], dd1[H], dd2[H], us[H], nus[H];
    __shared__ float psum[8 * H];
    __shared__ float red[4];
    __shared__ __align__(16) float4 part4[256];

    const int tid = threadIdx.x;
    const int lane = tid & 31;
    const int warp = tid >> 5;                    // 0..31

    // Phase A: reduce K1_BLOCKS partials (coalesced, 8-way group split)
    {
        const int i = tid & (H - 1);
        const int g = tid >> 7;                   // 0..7
        float s = 0.f;
        #pragma unroll 8
        for (int b = g; b < K1_BLOCKS; b += 8)
            s += g_part[b * H + i];
        psum[g * H + i] = s;
    }
    __syncthreads();
    if (tid < H) {
        float s = b0v[tid];
        #pragma unroll
        for (int g = 0; g < 8; g++) s += psum[g * H + tid];
        float a = tanhf(s);
        v[tid] = a;
        dd0[tid] = 1.f - a * a;
    }
    __syncthreads();

    // Forward: layer 0 (W1) + tanh
    fwd_matvec(W1, b1v, v, nv, warp, lane);
    __syncthreads();
    if (tid < H) { float a = tanhf(nv[tid]); v[tid] = a; dd1[tid] = 1.f - a * a; }
    __syncthreads();

    // Forward: layer 1 (W2) + tanh
    fwd_matvec(W2, b2v, v, nv, warp, lane);
    __syncthreads();
    if (tid < H) { float a = tanhf(nv[tid]); v[tid] = a; dd2[tid] = 1.f - a * a; }
    __syncthreads();

    // Forward: layer 2 (W3), no activation
    fwd_matvec(W3, b3v, v, nv, warp, lane);
    __syncthreads();
    if (tid < H) v[tid] = nv[tid];
    __syncthreads();

    // h = Wout . v + bout ; seed u = Wout
    if (tid < H) {
        float p = Wout[tid] * v[tid];
        #pragma unroll
        for (int off = 16; off; off >>= 1)
            p += __shfl_down_sync(0xffffffffu, p, off);
        if (lane == 0) red[warp] = p;             // warps 0..3
        us[tid] = Wout[tid];
    }
    __syncthreads();
    if (tid == 0) out[0] = red[0] + red[1] + red[2] + red[3] + boutv[0];
    __syncthreads();

    // Backward composition
    bwd_matvec(W3, us,  dd2, nus, part4, tid);
    bwd_matvec(W2, nus, dd1, us,  part4, tid);
    bwd_matvec(W1, us,  dd0, nus, part4, tid);
    if (tid < H) g_u[tid] = nus[tid];
}

// ---------------------------------------------------------------------------
// Kernel 3: out[1+j] = (sum_i u[i] * W0[i,j]) * 2 / (xmax[j]-xmin[j])
// 1024 blocks x 256 threads; block owns 32 float4-columns, threads split the
// 128-row sum 8 ways (16 independent LDG.128 per thread), smem combine.
// ---------------------------------------------------------------------------
__global__ void __launch_bounds__(K3_THREADS) k3_out(
        const float* __restrict__ W0,
        const float* __restrict__ xmax,
        const float* __restrict__ xmin,
        float* __restrict__ out) {
    __shared__ float us[H];
    __shared__ __align__(16) float4 part4[K3_THREADS];
    const int tid = threadIdx.x;
    if (tid < H) us[tid] = g_u[tid];
    __syncthreads();

    const int lane = tid & 31;                    // column-within-block
    const int ig = tid >> 5;                      // 0..7 row group
    const int c4 = blockIdx.x * K3_C4_PER_BLOCK + lane;   // global float4 col
    const float4* __restrict__ W4 = (const float4*)W0;
    const int rs4 = N_STATE / 4;

    float4 a = make_float4(0.f, 0.f, 0.f, 0.f);
    #pragma unroll
    for (int k = 0; k < 16; k++) {
        const int i = ig * 16 + k;
        float4 w = W4[i * rs4 + c4];
        float ui = us[i];
        a.x += ui * w.x; a.y += ui * w.y; a.z += ui * w.z; a.w += ui * w.w;
    }
    part4[tid] = a;
    __syncthreads();

    if (tid < 32) {
        float4 s = make_float4(0.f, 0.f, 0.f, 0.f);
        #pragma unroll
        for (int g = 0; g < 8; g++) {
            float4 p = part4[g * 32 + tid];
            s.x += p.x; s.y += p.y; s.z += p.z; s.w += p.w;
        }
        const int c4g = blockIdx.x * K3_C4_PER_BLOCK + tid;
        float4 mx = ((const float4*)xmax)[c4g];
        float4 mn = ((const float4*)xmin)[c4g];
        const int j = c4g * 4;
        out[1 + j + 0] = s.x * 2.f / (mx.x - mn.x);
        out[1 + j + 1] = s.y * 2.f / (mx.y - mn.y);
        out[1 + j + 2] = s.z * 2.f / (mx.z - mn.z);
        out[1 + j + 3] = s.w * 2.f / (mx.w - mn.w);
    }
}

// ---------------------------------------------------------------------------
extern "C" void kernel_launch(void* const* d_in, const int* in_sizes, int n_in,
                              void* d_out, int out_size) {
    const float* state = (const float*)d_in[0];
    const float* xmax  = (const float*)d_in[1];
    const float* xmin  = (const float*)d_in[2];
    const float* W0    = (const float*)d_in[3];
    const float* b0    = (const float*)d_in[4];
    const float* W1    = (const float*)d_in[5];
    const float* b1    = (const float*)d_in[6];
    const float* W2    = (const float*)d_in[7];
    const float* b2    = (const float*)d_in[8];
    const float* W3    = (const float*)d_in[9];
    const float* b3    = (const float*)d_in[10];
    const float* Wout  = (const float*)d_in[11];
    const float* bout  = (const float*)d_in[12];
    float* out = (float*)d_out;

    k1_matvec<<<K1_BLOCKS, K1_THREADS>>>(state, xmax, xmin, W0);
    k2_chain<<<1, K2_THREADS>>>(b0, W1, b1, W2, b2, W3, b3, Wout, bout, out);
    k3_out<<<K3_BLOCKS, K3_THREADS>>>(W0, xmax, xmin, out);
}